// round 1
// baseline (speedup 1.0000x reference)
#include <cuda_runtime.h>

#define TOKENS 8192
#define DM 1024
#define DH 4096
#define NE 8
#define NSLOTS (TOKENS * 2)

#define BM 128
#define BN 128
#define BK 8

// Scratch (device globals: allocation-free per harness rules)
__device__ float g_h[(size_t)NSLOTS * DH];   // routed hidden activations, 268 MB
__device__ int g_top2[TOKENS];
__device__ int g_counts[NE];
__device__ int g_offsets[NE];
__device__ int g_cursor[NE];
__device__ int g_tokens[NSLOTS];

__global__ void k_reset() {
    int i = threadIdx.x;
    if (i < NE) g_counts[i] = 0;
}

// One warp per token: logits = x0[t] @ Wg  (fp64 accumulate for ranking safety),
// pick top-2 expert indices (strict > == jax top_k tie-break: lower index wins).
__global__ void k_gating(const float* __restrict__ x0, const float* __restrict__ Wg) {
    int warp = threadIdx.x >> 5, lane = threadIdx.x & 31;
    int t = blockIdx.x * (blockDim.x >> 5) + warp;
    if (t >= TOKENS) return;
    double acc[NE];
#pragma unroll
    for (int e = 0; e < NE; e++) acc[e] = 0.0;
    const float* x = x0 + (size_t)t * DM;
    for (int k = lane; k < DM; k += 32) {
        float xv = x[k];
        const float4 w0 = *reinterpret_cast<const float4*>(Wg + (size_t)k * NE);
        const float4 w1 = *reinterpret_cast<const float4*>(Wg + (size_t)k * NE + 4);
        acc[0] += (double)xv * w0.x; acc[1] += (double)xv * w0.y;
        acc[2] += (double)xv * w0.z; acc[3] += (double)xv * w0.w;
        acc[4] += (double)xv * w1.x; acc[5] += (double)xv * w1.y;
        acc[6] += (double)xv * w1.z; acc[7] += (double)xv * w1.w;
    }
#pragma unroll
    for (int off = 16; off > 0; off >>= 1)
#pragma unroll
        for (int e = 0; e < NE; e++)
            acc[e] += __shfl_xor_sync(0xffffffffu, acc[e], off);
    if (lane == 0) {
        int i1 = 0; double v1 = acc[0];
#pragma unroll
        for (int e = 1; e < NE; e++) if (acc[e] > v1) { v1 = acc[e]; i1 = e; }
        int i2 = -1; double v2 = -1.0e300;
#pragma unroll
        for (int e = 0; e < NE; e++) if (e != i1 && acc[e] > v2) { v2 = acc[e]; i2 = e; }
        g_top2[t] = i1 | (i2 << 8);
        atomicAdd(&g_counts[i1], 1);
        atomicAdd(&g_counts[i2], 1);
    }
}

__global__ void k_scan() {
    int s = 0;
    for (int e = 0; e < NE; e++) { g_offsets[e] = s; g_cursor[e] = s; s += g_counts[e]; }
}

__global__ void k_scatter() {
    int t = blockIdx.x * blockDim.x + threadIdx.x;
    if (t >= TOKENS) return;
    int p = g_top2[t];
    g_tokens[atomicAdd(&g_cursor[p & 0xff], 1)] = t;
    g_tokens[atomicAdd(&g_cursor[(p >> 8) & 0xff], 1)] = t;
}

// GEMM1: g_h[slot, n] = relu(xl[tok(slot), :] @ W1[e] + b1[e])
// 128x128 tile, BK=8, 256 threads, 8x8 per-thread microtile.
__global__ __launch_bounds__(256) void k_gemm1(const float* __restrict__ xl,
                                               const float* __restrict__ W1,
                                               const float* __restrict__ b1) {
    const int e = blockIdx.z;
    const int cnt = g_counts[e];
    const int m0 = blockIdx.y * BM;
    if (m0 >= cnt) return;
    const int off = g_offsets[e];
    const int n0 = blockIdx.x * BN;

    __shared__ float As[BK][BM];
    __shared__ float Bs[BK][BN];

    const int tid = threadIdx.x;
    const int ar = tid >> 1;
    const int aq = (tid & 1) * 4;
    const int mload = m0 + ar;
    const int row = g_tokens[off + (mload < cnt ? mload : cnt - 1)];
    const float* aptr = xl + (size_t)row * DM + aq;

    const int bk = tid >> 5;
    const int bc = (tid & 31) * 4;
    const float* bptr = W1 + (size_t)e * DM * DH + (size_t)bk * DH + n0 + bc;

    const int ty = tid >> 4, tx = tid & 15;
    float acc[8][8];
#pragma unroll
    for (int i = 0; i < 8; i++)
#pragma unroll
        for (int j = 0; j < 8; j++) acc[i][j] = 0.f;

    for (int kt = 0; kt < DM / BK; kt++) {
        float4 av = *reinterpret_cast<const float4*>(aptr);
        float4 bv = *reinterpret_cast<const float4*>(bptr);
        As[aq + 0][ar] = av.x; As[aq + 1][ar] = av.y;
        As[aq + 2][ar] = av.z; As[aq + 3][ar] = av.w;
        *reinterpret_cast<float4*>(&Bs[bk][bc]) = bv;
        __syncthreads();
#pragma unroll
        for (int kk = 0; kk < BK; kk++) {
            float a[8], b[8];
            *(float4*)&a[0] = *(const float4*)&As[kk][ty * 8];
            *(float4*)&a[4] = *(const float4*)&As[kk][ty * 8 + 4];
            *(float4*)&b[0] = *(const float4*)&Bs[kk][tx * 8];
            *(float4*)&b[4] = *(const float4*)&Bs[kk][tx * 8 + 4];
#pragma unroll
            for (int i = 0; i < 8; i++)
#pragma unroll
                for (int j = 0; j < 8; j++) acc[i][j] += a[i] * b[j];
        }
        __syncthreads();
        aptr += BK;
        bptr += (size_t)BK * DH;
    }

    const float* be = b1 + (size_t)e * DH + n0 + tx * 8;
#pragma unroll
    for (int i = 0; i < 8; i++) {
        int mm = m0 + ty * 8 + i;
        if (mm >= cnt) break;
        float* crow = g_h + (size_t)(off + mm) * DH + n0 + tx * 8;
#pragma unroll
        for (int j = 0; j < 8; j += 4) {
            float4 v;
            v.x = fmaxf(acc[i][j + 0] + be[j + 0], 0.f);
            v.y = fmaxf(acc[i][j + 1] + be[j + 1], 0.f);
            v.z = fmaxf(acc[i][j + 2] + be[j + 2], 0.f);
            v.w = fmaxf(acc[i][j + 3] + be[j + 3], 0.f);
            *reinterpret_cast<float4*>(crow + j) = v;
        }
    }
}

// GEMM2: out[tok(slot), n] += g_h[slot, :] @ W2[e] + b2[e]  (atomic combine)
__global__ __launch_bounds__(256) void k_gemm2(const float* __restrict__ W2,
                                               const float* __restrict__ b2,
                                               float* __restrict__ out) {
    const int e = blockIdx.z;
    const int cnt = g_counts[e];
    const int m0 = blockIdx.y * BM;
    if (m0 >= cnt) return;
    const int off = g_offsets[e];
    const int n0 = blockIdx.x * BN;

    __shared__ float As[BK][BM];
    __shared__ float Bs[BK][BN];

    const int tid = threadIdx.x;
    const int ar = tid >> 1;
    const int aq = (tid & 1) * 4;
    const int mload = m0 + ar;
    const int slot = off + (mload < cnt ? mload : cnt - 1);
    const float* aptr = g_h + (size_t)slot * DH + aq;

    const int bk = tid >> 5;
    const int bc = (tid & 31) * 4;
    const float* bptr = W2 + (size_t)e * DH * DM + (size_t)bk * DM + n0 + bc;

    const int ty = tid >> 4, tx = tid & 15;
    float acc[8][8];
#pragma unroll
    for (int i = 0; i < 8; i++)
#pragma unroll
        for (int j = 0; j < 8; j++) acc[i][j] = 0.f;

    for (int kt = 0; kt < DH / BK; kt++) {
        float4 av = *reinterpret_cast<const float4*>(aptr);
        float4 bv = *reinterpret_cast<const float4*>(bptr);
        As[aq + 0][ar] = av.x; As[aq + 1][ar] = av.y;
        As[aq + 2][ar] = av.z; As[aq + 3][ar] = av.w;
        *reinterpret_cast<float4*>(&Bs[bk][bc]) = bv;
        __syncthreads();
#pragma unroll
        for (int kk = 0; kk < BK; kk++) {
            float a[8], b[8];
            *(float4*)&a[0] = *(const float4*)&As[kk][ty * 8];
            *(float4*)&a[4] = *(const float4*)&As[kk][ty * 8 + 4];
            *(float4*)&b[0] = *(const float4*)&Bs[kk][tx * 8];
            *(float4*)&b[4] = *(const float4*)&Bs[kk][tx * 8 + 4];
#pragma unroll
            for (int i = 0; i < 8; i++)
#pragma unroll
                for (int j = 0; j < 8; j++) acc[i][j] += a[i] * b[j];
        }
        __syncthreads();
        aptr += BK;
        bptr += (size_t)BK * DM;
    }

    const float* be = b2 + (size_t)e * DM + n0 + tx * 8;
#pragma unroll
    for (int i = 0; i < 8; i++) {
        int mm = m0 + ty * 8 + i;
        if (mm >= cnt) break;
        int tok = g_tokens[off + mm];
        float* crow = out + (size_t)tok * DM + n0 + tx * 8;
#pragma unroll
        for (int j = 0; j < 8; j++)
            atomicAdd(crow + j, acc[i][j] + be[j]);
    }
}

extern "C" void kernel_launch(void* const* d_in, const int* in_sizes, int n_in,
                              void* d_out, int out_size) {
    const float* xl = (const float*)d_in[0];
    const float* x0 = (const float*)d_in[1];
    const float* Wg = (const float*)d_in[2];
    const float* W1 = (const float*)d_in[3];
    const float* b1 = (const float*)d_in[4];
    const float* W2 = (const float*)d_in[5];
    const float* b2 = (const float*)d_in[6];
    float* out = (float*)d_out;

    cudaMemsetAsync(out, 0, (size_t)TOKENS * DM * sizeof(float));
    k_reset<<<1, 32>>>();
    k_gating<<<TOKENS / 8, 256>>>(x0, Wg);
    k_scan<<<1, 1>>>();
    k_scatter<<<TOKENS / 256, 256>>>();
    k_gemm1<<<dim3(DH / BN, TOKENS / BM, NE), 256>>>(xl, W1, b1);
    k_gemm2<<<dim3(DM / BN, TOKENS / BM, NE), 256>>>(W2, b2, out);
}

// round 3
// speedup vs baseline: 2.4626x; 2.4626x over previous
#include <cuda_runtime.h>
#include <cuda_bf16.h>
#include <cstdint>

#define TOKENS 8192
#define DM 1024
#define DH 4096
#define NE 8
#define NSLOTS (TOKENS * 2)

// GEMM tiling
#define BM 128
#define BN 128
#define BK 32
#define STAGES 4
#define PITCH 40                       // bf16 elements per smem row (32 + 8 pad)
#define TILE_BYTES (128 * PITCH * 2)   // 10240 B per (tensor, half)
#define OFF_AH 0
#define OFF_AL (TILE_BYTES)
#define OFF_BH (2 * TILE_BYTES)
#define OFF_BL (3 * TILE_BYTES)
#define STAGE_BYTES (4 * TILE_BYTES)   // 40960
#define SMEM_TOTAL (STAGES * STAGE_BYTES)

// ---------------- scratch globals (allocation-free rule) ----------------
__device__ __nv_bfloat16 g_xl_hi[(size_t)TOKENS * DM];
__device__ __nv_bfloat16 g_xl_lo[(size_t)TOKENS * DM];
__device__ __nv_bfloat16 g_w1t_hi[(size_t)NE * DH * DM];   // [E][N=DH][K=DM]
__device__ __nv_bfloat16 g_w1t_lo[(size_t)NE * DH * DM];
__device__ __nv_bfloat16 g_w2t_hi[(size_t)NE * DM * DH];   // [E][N=DM][K=DH]
__device__ __nv_bfloat16 g_w2t_lo[(size_t)NE * DM * DH];
__device__ __nv_bfloat16 g_h_hi[(size_t)NSLOTS * DH];
__device__ __nv_bfloat16 g_h_lo[(size_t)NSLOTS * DH];
__device__ int g_top2[TOKENS];
__device__ int g_counts[NE];
__device__ int g_offsets[NE];
__device__ int g_cursor[NE];
__device__ int g_tokens[NSLOTS];

// ---------------- PTX helpers ----------------
__device__ __forceinline__ uint32_t smem_u32(const void* p) {
    uint32_t a;
    asm("{ .reg .u64 t; cvta.to.shared.u64 t, %1; cvt.u32.u64 %0, t; }" : "=r"(a) : "l"(p));
    return a;
}
__device__ __forceinline__ void cp_async16(uint32_t dst, const void* src) {
    asm volatile("cp.async.cg.shared.global [%0], [%1], 16;" :: "r"(dst), "l"(src));
}
__device__ __forceinline__ void cp_commit() { asm volatile("cp.async.commit_group;" ::: "memory"); }
template <int N>
__device__ __forceinline__ void cp_wait() { asm volatile("cp.async.wait_group %0;" :: "n"(N) : "memory"); }

__device__ __forceinline__ void ldsm4(uint32_t* r, uint32_t addr) {
    asm volatile("ldmatrix.sync.aligned.m8n8.x4.shared.b16 {%0,%1,%2,%3}, [%4];"
                 : "=r"(r[0]), "=r"(r[1]), "=r"(r[2]), "=r"(r[3]) : "r"(addr));
}
__device__ __forceinline__ void mma_bf16(float* c, const uint32_t* a, const uint32_t* b) {
    asm volatile(
        "mma.sync.aligned.m16n8k16.row.col.f32.bf16.bf16.f32 "
        "{%0,%1,%2,%3}, {%4,%5,%6,%7}, {%8,%9}, {%0,%1,%2,%3};"
        : "+f"(c[0]), "+f"(c[1]), "+f"(c[2]), "+f"(c[3])
        : "r"(a[0]), "r"(a[1]), "r"(a[2]), "r"(a[3]), "r"(b[0]), "r"(b[1]));
}

// ---------------- routing (proven in round 1) ----------------
__global__ void k_reset() { if (threadIdx.x < NE) g_counts[threadIdx.x] = 0; }

__global__ void k_gating(const float* __restrict__ x0, const float* __restrict__ Wg) {
    int warp = threadIdx.x >> 5, lane = threadIdx.x & 31;
    int t = blockIdx.x * (blockDim.x >> 5) + warp;
    if (t >= TOKENS) return;
    double acc[NE];
#pragma unroll
    for (int e = 0; e < NE; e++) acc[e] = 0.0;
    const float* x = x0 + (size_t)t * DM;
    for (int k = lane; k < DM; k += 32) {
        float xv = x[k];
        const float4 w0 = *reinterpret_cast<const float4*>(Wg + (size_t)k * NE);
        const float4 w1 = *reinterpret_cast<const float4*>(Wg + (size_t)k * NE + 4);
        acc[0] += (double)xv * w0.x; acc[1] += (double)xv * w0.y;
        acc[2] += (double)xv * w0.z; acc[3] += (double)xv * w0.w;
        acc[4] += (double)xv * w1.x; acc[5] += (double)xv * w1.y;
        acc[6] += (double)xv * w1.z; acc[7] += (double)xv * w1.w;
    }
#pragma unroll
    for (int off = 16; off > 0; off >>= 1)
#pragma unroll
        for (int e = 0; e < NE; e++) acc[e] += __shfl_xor_sync(0xffffffffu, acc[e], off);
    if (lane == 0) {
        int i1 = 0; double v1 = acc[0];
#pragma unroll
        for (int e = 1; e < NE; e++) if (acc[e] > v1) { v1 = acc[e]; i1 = e; }
        int i2 = -1; double v2 = -1.0e300;
#pragma unroll
        for (int e = 0; e < NE; e++) if (e != i1 && acc[e] > v2) { v2 = acc[e]; i2 = e; }
        g_top2[t] = i1 | (i2 << 8);
        atomicAdd(&g_counts[i1], 1);
        atomicAdd(&g_counts[i2], 1);
    }
}

__global__ void k_scan() {
    int s = 0;
    for (int e = 0; e < NE; e++) { g_offsets[e] = s; g_cursor[e] = s; s += g_counts[e]; }
}

__global__ void k_scatter() {
    int t = blockIdx.x * blockDim.x + threadIdx.x;
    if (t >= TOKENS) return;
    int p = g_top2[t];
    g_tokens[atomicAdd(&g_cursor[p & 0xff], 1)] = t;
    g_tokens[atomicAdd(&g_cursor[(p >> 8) & 0xff], 1)] = t;
}

// ---------------- preprocessing: fp32 -> bf16 hi/lo ----------------
__global__ void k_cvt_x(const float* __restrict__ x) {
    size_t i = (size_t)blockIdx.x * blockDim.x + threadIdx.x;
    float v = x[i];
    __nv_bfloat16 h = __float2bfloat16(v);
    g_xl_hi[i] = h;
    g_xl_lo[i] = __float2bfloat16(v - __bfloat162float(h));
}

// transpose-convert: W[e][k][n] (fp32) -> out[e][n][k] (bf16 hi/lo). which: 0=W1, 1=W2
__global__ void k_wt(const float* __restrict__ W, int K, int N, int which) {
    __shared__ float t[32][33];
    int e = blockIdx.z;
    int n0 = blockIdx.x * 32, k0 = blockIdx.y * 32;
    const float* Wp = W + (size_t)e * K * N;
    __nv_bfloat16* Ohi = which ? g_w2t_hi : g_w1t_hi;
    __nv_bfloat16* Olo = which ? g_w2t_lo : g_w1t_lo;
    int tx = threadIdx.x, ty = threadIdx.y;
#pragma unroll
    for (int j = 0; j < 4; j++)
        t[ty + j * 8][tx] = Wp[(size_t)(k0 + ty + j * 8) * N + n0 + tx];
    __syncthreads();
#pragma unroll
    for (int j = 0; j < 4; j++) {
        int n = n0 + ty + j * 8;
        float v = t[tx][ty + j * 8];
        __nv_bfloat16 h = __float2bfloat16(v);
        size_t o = ((size_t)e * N + n) * K + k0 + tx;
        Ohi[o] = h;
        Olo[o] = __float2bfloat16(v - __bfloat162float(h));
    }
}

// ---------------- HMMA split-bf16 grouped GEMM ----------------
// 128x128x32 tile, 8 warps (2x4), 64x32 warp tile, mma.m16n8k16, 4-stage cp.async.

__device__ __forceinline__ void compute_stage(uint32_t st, float acc[4][4][4],
                                              uint32_t a_off, uint32_t b_off) {
#pragma unroll
    for (int k16 = 0; k16 < 2; k16++) {
        const uint32_t ab = st + a_off + k16 * 32;
        const uint32_t bb = st + b_off + k16 * 32;
        uint32_t af[4][4], bf[2][4], bl[2][4];
#pragma unroll
        for (int mt = 0; mt < 4; mt++) ldsm4(af[mt], ab + OFF_AH + mt * (16 * PITCH * 2));
#pragma unroll
        for (int p = 0; p < 2; p++)   ldsm4(bf[p], bb + OFF_BH + p * (16 * PITCH * 2));
        // pass 1: Ahi * Bhi
#pragma unroll
        for (int mt = 0; mt < 4; mt++)
#pragma unroll
            for (int nt = 0; nt < 4; nt++)
                mma_bf16(acc[mt][nt], af[mt], &bf[nt >> 1][(nt & 1) * 2]);
        // pass 2: Ahi * Blo
#pragma unroll
        for (int p = 0; p < 2; p++)   ldsm4(bl[p], bb + OFF_BL + p * (16 * PITCH * 2));
#pragma unroll
        for (int mt = 0; mt < 4; mt++)
#pragma unroll
            for (int nt = 0; nt < 4; nt++)
                mma_bf16(acc[mt][nt], af[mt], &bl[nt >> 1][(nt & 1) * 2]);
        // pass 3: Alo * Bhi  (reuse af regs)
#pragma unroll
        for (int mt = 0; mt < 4; mt++) ldsm4(af[mt], ab + OFF_AL + mt * (16 * PITCH * 2));
#pragma unroll
        for (int mt = 0; mt < 4; mt++)
#pragma unroll
            for (int nt = 0; nt < 4; nt++)
                mma_bf16(acc[mt][nt], af[mt], &bf[nt >> 1][(nt & 1) * 2]);
    }
}

template <int KT, int NTOT, bool IS_G1>
__global__ __launch_bounds__(256, 1) void k_hmma(const float* __restrict__ bias,
                                                 float* __restrict__ out) {
    const int e = blockIdx.z;
    const int cnt = g_counts[e];
    const int m0 = blockIdx.y * BM;
    if (m0 >= cnt) return;
    const int off = g_offsets[e];
    const int n0 = blockIdx.x * BN;
    const int tid = threadIdx.x;

    extern __shared__ char smem[];
    __shared__ int s_rows[BM];
    const uint32_t sb = smem_u32(smem);

    {   // A-row gather list (dup last row for tail; results discarded)
        int mm = m0 + tid;
        if (tid < BM) {
            int mc = mm < cnt ? mm : cnt - 1;
            s_rows[tid] = IS_G1 ? g_tokens[off + mc] : (off + mc);
        }
    }
    __syncthreads();

    const __nv_bfloat16* Ahi = IS_G1 ? g_xl_hi : g_h_hi;
    const __nv_bfloat16* Alo = IS_G1 ? g_xl_lo : g_h_lo;
    const __nv_bfloat16* Bhi = (IS_G1 ? g_w1t_hi : g_w2t_hi) + ((size_t)e * NTOT + n0) * KT;
    const __nv_bfloat16* Blo = (IS_G1 ? g_w1t_lo : g_w2t_lo) + ((size_t)e * NTOT + n0) * KT;

    // per-thread cp.async plan: 2 reps x (r = idx/4 row, c = idx%4 16B-chunk)
    const int r0 = tid >> 2, c0 = (tid & 3);
    const int r1 = (tid + 256) >> 2, c1 = (tid & 3);
    const uint32_t d0 = r0 * (PITCH * 2) + c0 * 16;
    const uint32_t d1 = r1 * (PITCH * 2) + c1 * 16;
    const __nv_bfloat16* ah0 = Ahi + (size_t)s_rows[r0] * KT + c0 * 8;
    const __nv_bfloat16* al0 = Alo + (size_t)s_rows[r0] * KT + c0 * 8;
    const __nv_bfloat16* ah1 = Ahi + (size_t)s_rows[r1] * KT + c1 * 8;
    const __nv_bfloat16* al1 = Alo + (size_t)s_rows[r1] * KT + c1 * 8;
    const __nv_bfloat16* bh0 = Bhi + (size_t)r0 * KT + c0 * 8;
    const __nv_bfloat16* bl0 = Blo + (size_t)r0 * KT + c0 * 8;
    const __nv_bfloat16* bh1 = Bhi + (size_t)r1 * KT + c1 * 8;
    const __nv_bfloat16* bl1 = Blo + (size_t)r1 * KT + c1 * 8;

#define FILL(sidx, k0_)  do {                                              \
        uint32_t _s = sb + (sidx) * STAGE_BYTES;                           \
        cp_async16(_s + OFF_AH + d0, ah0 + (k0_));                         \
        cp_async16(_s + OFF_AL + d0, al0 + (k0_));                         \
        cp_async16(_s + OFF_BH + d0, bh0 + (k0_));                         \
        cp_async16(_s + OFF_BL + d0, bl0 + (k0_));                         \
        cp_async16(_s + OFF_AH + d1, ah1 + (k0_));                         \
        cp_async16(_s + OFF_AL + d1, al1 + (k0_));                         \
        cp_async16(_s + OFF_BH + d1, bh1 + (k0_));                         \
        cp_async16(_s + OFF_BL + d1, bl1 + (k0_));                         \
    } while (0)

    // lane fragment offsets (bytes within stage)
    const int lane = tid & 31, wid = tid >> 5;
    const int warp_m = wid >> 2, warp_n = wid & 3;
    const uint32_t a_off = (warp_m * 64 + (lane & 15)) * (PITCH * 2) + (lane >> 4) * 16;
    const uint32_t b_off = (warp_n * 32 + ((lane >> 4) << 3) + (lane & 7)) * (PITCH * 2)
                           + ((lane >> 3) & 1) * 16;

    float acc[4][4][4];
#pragma unroll
    for (int i = 0; i < 4; i++)
#pragma unroll
        for (int j = 0; j < 4; j++)
#pragma unroll
            for (int q = 0; q < 4; q++) acc[i][j][q] = 0.f;

    constexpr int NKC = KT / BK;
#pragma unroll
    for (int s = 0; s < STAGES - 1; s++) { FILL(s, s * BK); cp_commit(); }

    for (int kc = 0; kc < NKC; kc++) {
        cp_wait<STAGES - 2>();
        __syncthreads();
        const int nf = kc + STAGES - 1;
        if (nf < NKC) FILL(nf % STAGES, nf * BK);
        cp_commit();
        compute_stage(sb + (kc % STAGES) * STAGE_BYTES, acc, a_off, b_off);
    }
#undef FILL

    // ---- epilogue ----
    const int g = lane >> 2, c2 = (lane & 3) * 2;
    const float* bp = bias + (size_t)e * NTOT;
#pragma unroll
    for (int mt = 0; mt < 4; mt++) {
#pragma unroll
        for (int nt = 0; nt < 4; nt++) {
            const int n = n0 + warp_n * 32 + nt * 8 + c2;
            const float bv0 = __ldg(bp + n), bv1 = __ldg(bp + n + 1);
#pragma unroll
            for (int h = 0; h < 2; h++) {
                const int m = m0 + warp_m * 64 + mt * 16 + g + h * 8;
                if (m >= cnt) continue;
                float v0 = acc[mt][nt][h * 2 + 0] + bv0;
                float v1 = acc[mt][nt][h * 2 + 1] + bv1;
                if (IS_G1) {
                    v0 = fmaxf(v0, 0.f); v1 = fmaxf(v1, 0.f);
                    __nv_bfloat162 h2 = __floats2bfloat162_rn(v0, v1);
                    __nv_bfloat162 l2 = __floats2bfloat162_rn(
                        v0 - __bfloat162float(h2.x), v1 - __bfloat162float(h2.y));
                    const size_t o = (size_t)(off + m) * DH + n;
                    *reinterpret_cast<uint32_t*>(g_h_hi + o) = *reinterpret_cast<uint32_t*>(&h2);
                    *reinterpret_cast<uint32_t*>(g_h_lo + o) = *reinterpret_cast<uint32_t*>(&l2);
                } else {
                    const int tok = g_tokens[off + m];
                    atomicAdd(out + (size_t)tok * DM + n, v0);
                    atomicAdd(out + (size_t)tok * DM + n + 1, v1);
                }
            }
        }
    }
}

// ---------------- launch ----------------
extern "C" void kernel_launch(void* const* d_in, const int* in_sizes, int n_in,
                              void* d_out, int out_size) {
    const float* xl = (const float*)d_in[0];
    const float* x0 = (const float*)d_in[1];
    const float* Wg = (const float*)d_in[2];
    const float* W1 = (const float*)d_in[3];
    const float* b1 = (const float*)d_in[4];
    const float* W2 = (const float*)d_in[5];
    const float* b2 = (const float*)d_in[6];
    float* out = (float*)d_out;

    cudaFuncSetAttribute((const void*)k_hmma<DM, DH, true>,
                         cudaFuncAttributeMaxDynamicSharedMemorySize, SMEM_TOTAL);
    cudaFuncSetAttribute((const void*)k_hmma<DH, DM, false>,
                         cudaFuncAttributeMaxDynamicSharedMemorySize, SMEM_TOTAL);

    cudaMemsetAsync(out, 0, (size_t)TOKENS * DM * sizeof(float));
    k_reset<<<1, 32>>>();
    k_gating<<<TOKENS / 8, 256>>>(x0, Wg);
    k_scan<<<1, 1>>>();
    k_scatter<<<TOKENS / 256, 256>>>();

    k_cvt_x<<<(TOKENS * DM) / 256, 256>>>(xl);
    k_wt<<<dim3(DH / 32, DM / 32, NE), dim3(32, 8)>>>(W1, DM, DH, 0);
    k_wt<<<dim3(DM / 32, DH / 32, NE), dim3(32, 8)>>>(W2, DH, DM, 1);

    // GEMM1: relu(xl @ W1[e] + b1[e]) -> h (bf16 hi/lo), gathered rows
    k_hmma<DM, DH, true><<<dim3(DH / BN, TOKENS / BM, NE), 256, SMEM_TOTAL>>>(b1, nullptr);
    // GEMM2: h @ W2[e] + b2[e] -> atomic combine into out
    k_hmma<DH, DM, false><<<dim3(DM / BN, TOKENS / BM, NE), 256, SMEM_TOTAL>>>(b2, out);
}